// round 16
// baseline (speedup 1.0000x reference)
#include <cuda_runtime.h>
#include <math.h>

#define BG 256
#define TT 64
#define PP 10
#define DD 128
#define HH 64
#define BT (BG*TT)   // 16384
#define GPB 8        // lstm games per block

// ---- device scratch (allocation-free) ----
__device__ float g_z[BT*PP*64];            // SGCN output z  [bt][p][64]
__device__ float g_gih[(size_t)BT*PP*256]; // gates_ih+bias  [bt][p][256]
__device__ float4 g_WbF[4096];             // base W tf32 frags [s][q][kf][fp][lane]
__device__ float4 g_WdF[7168];             // deep W tf32 frags [s][layer][q][kf][fp][lane]
__device__ float2 g_WihF[PP*8*8*4*32];     // gih B frags [p][w][kf][nb][lane]

// ---- tf32 helpers ----
__device__ __forceinline__ float to_tf32(float x){
    float y; asm("cvt.rna.tf32.f32 %0, %1;" : "=f"(y) : "f"(x)); return y;
}
// D = A(16x8,row) * B(8x8,col) + D, tf32 inputs, f32 accum
__device__ __forceinline__ void mma_tf32(float* c, const float* a, float b0, float b1){
    const unsigned* A = (const unsigned*)a;
    unsigned B0 = __float_as_uint(b0), B1 = __float_as_uint(b1);
    asm volatile(
        "mma.sync.aligned.m16n8k8.row.col.f32.tf32.tf32.f32 "
        "{%0,%1,%2,%3}, {%4,%5,%6,%7}, {%8,%9}, {%0,%1,%2,%3};\n"
        : "+f"(c[0]), "+f"(c[1]), "+f"(c[2]), "+f"(c[3])
        : "r"(A[0]), "r"(A[1]), "r"(A[2]), "r"(A[3]), "r"(B0), "r"(B1));
}

// fast activations
__device__ __forceinline__ float tanh_mufu(float x){
    float y; asm("tanh.approx.f32 %0, %1;" : "=f"(y) : "f"(x)); return y;
}
__device__ __forceinline__ float sigmoid_fast(float v){
    return __fdividef(1.0f, 1.0f + __expf(-v));
}
__device__ __forceinline__ float tanh_fast(float v){
    return __fdividef(2.0f, 1.0f + __expf(-2.0f*v)) - 1.0f;
}

// ------------------------------------------------------------------
// Kernel 0: weight packing -> tf32 mma B-fragments (base, deep, W_ih)
// ------------------------------------------------------------------
__global__ void transform_weights(
    const float* __restrict__ Wpb, const float* __restrict__ Wnb,
    const float* __restrict__ Wpd, const float* __restrict__ Wnd,
    const float* __restrict__ Wih)
{
    int idx = blockIdx.x*blockDim.x + threadIdx.x;
    if (idx < 4096){
        // base B frags: [s][q][kf][fp][lane]
        int lane = idx & 31; int t = idx >> 5;
        int fp = t & 1; t >>= 1;
        int kf = t & 7; t >>= 3;
        int q  = t & 3; int s = t >> 2;
        const float* W = s ? Wnb : Wpb;           // [256][32]
        int kb = q*64 + kf*8 + (lane & 3);
        int n0 = lane >> 2;
        int f0 = fp*2, f1 = fp*2 + 1;
        g_WbF[idx] = make_float4(
            to_tf32(W[(kb  )*32 + f0*8 + n0]), to_tf32(W[(kb+4)*32 + f0*8 + n0]),
            to_tf32(W[(kb  )*32 + f1*8 + n0]), to_tf32(W[(kb+4)*32 + f1*8 + n0]));
    } else if (idx < 4096 + 7168){
        // deep B frags: [s][layer][q][kf][fp][lane]
        int i2 = idx - 4096;
        int lane = i2 & 31; int t = i2 >> 5;
        int fp = t & 1; t >>= 1;
        int kf = t % 7; t /= 7;
        int q  = t & 3; t >>= 2;
        int layer = t & 1; int s = t >> 1;
        const float* W = (s ? Wnd : Wpd) + layer*224*32;   // [224][32]
        int kb = q*56 + kf*8 + (lane & 3);
        int n0 = lane >> 2;
        int f0 = fp*2, f1 = fp*2 + 1;
        g_WdF[i2] = make_float4(
            to_tf32(W[(kb  )*32 + f0*8 + n0]), to_tf32(W[(kb+4)*32 + f0*8 + n0]),
            to_tf32(W[(kb  )*32 + f1*8 + n0]), to_tf32(W[(kb+4)*32 + f1*8 + n0]));
    } else if (idx < 4096 + 7168 + PP*8*8*4*32){
        // gih B frags: [p][w][kf][nb][lane];  B[k][n] = Wih[p][n][k]
        int i3 = idx - (4096 + 7168);
        int lane = i3 & 31; int t = i3 >> 5;
        int nb = t & 3; t >>= 2;
        int kf = t & 7; t >>= 3;
        int w  = t & 7; int p = t >> 3;
        int g0 = w*32 + nb*8 + (lane >> 2);
        int k  = kf*8 + (lane & 3);
        const float* W = Wih + (size_t)p*16384 + g0*64;
        g_WihF[i3] = make_float2(to_tf32(W[k]), to_tf32(W[k+4]));
    }
}

// ------------------------------------------------------------------
// Kernel 1: SGCN (exact Round-14 version — tf32 mma, passed).
// ------------------------------------------------------------------
__global__ __launch_bounds__(256) void sgcn_kernel(
    const float* __restrict__ x,
    const float* __restrict__ Apos, const float* __restrict__ Aneg,
    const float* __restrict__ bpb,  const float* __restrict__ bnb,
    const float* __restrict__ bpd,  const float* __restrict__ bnd)
{
    __shared__ __align__(16) float xs[PP*DD];
    __shared__ float Asm[2][PP*PP];
    __shared__ float rs[2][PP];
    __shared__ __align__(16) float aggx[2*PP*DD];
    __shared__ __align__(16) float cat[6*PP*32];
    __shared__ float part[4*2*PP*32];

    const int bt  = blockIdx.x;
    const int tid = threadIdx.x;
    const int w   = tid >> 5;
    const int l   = tid & 31;
    const int s   = w & 1;
    const int q   = w >> 1;
    const int gid = l >> 2;
    const int tig = l & 3;

    {
        const float4* x4 = (const float4*)(x + (size_t)bt*PP*DD);
        float4* xs4 = (float4*)xs;
        for (int i = tid; i < PP*DD/4; i += 256) xs4[i] = x4[i];
    }
    if (tid < 200){
        int ss = tid/100, idx = tid - ss*100;
        Asm[ss][idx] = (ss ? Aneg : Apos)[(size_t)bt*100 + idx];
    }
    __syncthreads();
    if (tid < 20){
        int ss = tid/10, r = tid - ss*10;
        float sum = 0.f;
        #pragma unroll
        for (int j=0;j<10;j++) sum += Asm[ss][r*10+j];
        rs[ss][r] = __fdividef(1.0f, sum + 1e-8f);
    }
    __syncthreads();
    if (tid < 200){
        int ss = tid/100, idx = tid - ss*100;
        Asm[ss][idx] *= rs[ss][idx/10];
    }
    __syncthreads();

    {
        float4* ag4 = (float4*)aggx;
        const float4* xs4 = (const float4*)xs;
        for (int o = tid; o < 2*PP*32; o += 256){
            int ss = o / 320; int rem = o - ss*320;
            int r = rem >> 5; int d4 = rem & 31;
            float4 sum = make_float4(0.f,0.f,0.f,0.f);
            #pragma unroll
            for (int j=0;j<10;j++){
                float a = Asm[ss][r*10+j];
                float4 xv = xs4[j*32 + d4];
                sum.x += a*xv.x; sum.y += a*xv.y; sum.z += a*xv.z; sum.w += a*xv.w;
            }
            ag4[o] = sum;
        }
    }
    __syncthreads();

    // base matmul (tensor cores)
    {
        const float* src = (q < 2) ? (aggx + s*1280 + q*64) : (xs + (q-2)*64);
        float a[8][4];
        #pragma unroll
        for (int kf=0; kf<8; kf++){
            int c0 = kf*8 + tig;
            a[kf][0] = to_tf32(src[gid*128 + c0]);
            a[kf][1] = (gid<2) ? to_tf32(src[(gid+8)*128 + c0]) : 0.f;
            a[kf][2] = to_tf32(src[gid*128 + c0 + 4]);
            a[kf][3] = (gid<2) ? to_tf32(src[(gid+8)*128 + c0 + 4]) : 0.f;
        }
        float acc[4][4];
        #pragma unroll
        for (int f=0; f<4; f++){
            #pragma unroll
            for (int e=0; e<4; e++) acc[f][e] = 0.f;
        }
        const float4* BF = g_WbF + (size_t)((s*4+q)*8)*2*32;
        #pragma unroll
        for (int kf=0; kf<8; kf++){
            float4 b01 = BF[(kf*2+0)*32 + l];
            float4 b23 = BF[(kf*2+1)*32 + l];
            mma_tf32(acc[0], a[kf], b01.x, b01.y);
            mma_tf32(acc[1], a[kf], b01.z, b01.w);
            mma_tf32(acc[2], a[kf], b23.x, b23.y);
            mma_tf32(acc[3], a[kf], b23.z, b23.w);
        }
        float* pp = part + ((q*2+s)*10)*32;
        #pragma unroll
        for (int f=0; f<4; f++){
            int n0 = f*8 + tig*2;
            pp[gid*32 + n0]     = acc[f][0];
            pp[gid*32 + n0 + 1] = acc[f][1];
            if (gid < 2){
                pp[(gid+8)*32 + n0]     = acc[f][2];
                pp[(gid+8)*32 + n0 + 1] = acc[f][3];
            }
        }
    }
    __syncthreads();
    for (int o=tid; o<640; o+=256){
        int ss = o/320, rem = o - ss*320, r = rem>>5, col = rem&31;
        float v = (ss ? bnb : bpb)[col];
        #pragma unroll
        for (int qq=0;qq<4;qq++) v += part[((qq*2+ss)*10+r)*32+col];
        cat[(4+ss)*320 + r*32 + col] = tanh_mufu(v);
    }
    __syncthreads();

    for (int layer=0; layer<2; layer++){
        for (int o=tid; o<320; o+=256){
            int m = o/80, rem = o - m*80, r = rem>>3, c4 = (rem&7)*4;
            int as = m>>1, hsn = m&1;
            float4 sum = make_float4(0.f,0.f,0.f,0.f);
            #pragma unroll
            for (int j=0;j<10;j++){
                float a = Asm[as][r*10+j];
                float4 h = *(const float4*)&cat[(4+hsn)*320 + j*32 + c4];
                sum.x += a*h.x; sum.y += a*h.y; sum.z += a*h.z; sum.w += a*h.w;
            }
            *(float4*)&cat[m*320 + r*32 + c4] = sum;
        }
        __syncthreads();
        {
            float a[7][4];
            #pragma unroll
            for (int kf=0; kf<7; kf++){
                int k0 = q*56 + kf*8;
                int blk = k0 >> 5, ko = k0 & 31;
                const float* srcp = cat + ((blk<6) ? blk : (4+s))*320;
                int c0 = ko + tig;
                a[kf][0] = to_tf32(srcp[gid*32 + c0]);
                a[kf][1] = (gid<2) ? to_tf32(srcp[(gid+8)*32 + c0]) : 0.f;
                a[kf][2] = to_tf32(srcp[gid*32 + c0 + 4]);
                a[kf][3] = (gid<2) ? to_tf32(srcp[(gid+8)*32 + c0 + 4]) : 0.f;
            }
            float acc[4][4];
            #pragma unroll
            for (int f=0; f<4; f++){
                #pragma unroll
                for (int e=0; e<4; e++) acc[f][e] = 0.f;
            }
            const float4* BF = g_WdF + (size_t)(((s*2+layer)*4 + q)*7)*2*32;
            #pragma unroll
            for (int kf=0; kf<7; kf++){
                float4 b01 = BF[(kf*2+0)*32 + l];
                float4 b23 = BF[(kf*2+1)*32 + l];
                mma_tf32(acc[0], a[kf], b01.x, b01.y);
                mma_tf32(acc[1], a[kf], b01.z, b01.w);
                mma_tf32(acc[2], a[kf], b23.x, b23.y);
                mma_tf32(acc[3], a[kf], b23.z, b23.w);
            }
            float* pp = part + ((q*2+s)*10)*32;
            #pragma unroll
            for (int f=0; f<4; f++){
                int n0 = f*8 + tig*2;
                pp[gid*32 + n0]     = acc[f][0];
                pp[gid*32 + n0 + 1] = acc[f][1];
                if (gid < 2){
                    pp[(gid+8)*32 + n0]     = acc[f][2];
                    pp[(gid+8)*32 + n0 + 1] = acc[f][3];
                }
            }
        }
        __syncthreads();
        for (int o=tid; o<640; o+=256){
            int ss = o/320, rem = o - ss*320, r = rem>>5, col = rem&31;
            float v = (ss ? bnd : bpd)[layer*32+col];
            #pragma unroll
            for (int qq=0;qq<4;qq++) v += part[((qq*2+ss)*10+r)*32+col];
            cat[(4+ss)*320 + r*32 + col] = tanh_mufu(v);
        }
        __syncthreads();
    }

    float* zo = g_z + (size_t)bt*PP*64;
    for (int o=tid; o<640; o+=256){
        int r = o>>6, c = o&63, ss = c>>5, cc = c&31;
        zo[o] = cat[(4+ss)*320 + r*32 + cc];
    }
}

// ------------------------------------------------------------------
// Kernel 2: gates_ih on tensor cores.
// Block = (p, 32 rows), 8 warps; warp w covers gates [w*32, w*32+32).
// grid: (BT/32, PP) = (512, 10).
// ------------------------------------------------------------------
__global__ __launch_bounds__(256) void gih_kernel(
    const float* __restrict__ bih, const float* __restrict__ bhh)
{
    __shared__ __align__(16) float zs[32*64];   // 8KB
    __shared__ float bsm[256];

    const int p   = blockIdx.y;
    const int r0  = blockIdx.x * 32;
    const int tid = threadIdx.x;
    const int w   = tid >> 5;
    const int l   = tid & 31;
    const int gid = l >> 2;
    const int tig = l & 3;

    {   // z tile: 512 float4
        float4* zs4 = (float4*)zs;
        for (int i = tid; i < 512; i += 256){
            int rr = i >> 4, d4 = i & 15;
            zs4[i] = *(const float4*)&g_z[((size_t)(r0+rr)*10 + p)*64 + d4*4];
        }
    }
    bsm[tid] = bih[p*256+tid] + bhh[p*256+tid];
    __syncthreads();

    float acc[2][4][4];
    #pragma unroll
    for (int mt=0; mt<2; mt++)
        #pragma unroll
        for (int nb=0; nb<4; nb++)
            #pragma unroll
            for (int e=0; e<4; e++) acc[mt][nb][e] = 0.f;

    const float2* BF = g_WihF + (size_t)(p*8 + w)*8*4*32;

    #pragma unroll
    for (int kf=0; kf<8; kf++){
        int c0 = kf*8 + tig;
        float a0[4], a1[4];
        a0[0] = to_tf32(zs[ gid      *64 + c0]);
        a0[1] = to_tf32(zs[(gid+8)   *64 + c0]);
        a0[2] = to_tf32(zs[ gid      *64 + c0 + 4]);
        a0[3] = to_tf32(zs[(gid+8)   *64 + c0 + 4]);
        a1[0] = to_tf32(zs[(gid+16)  *64 + c0]);
        a1[1] = to_tf32(zs[(gid+24)  *64 + c0]);
        a1[2] = to_tf32(zs[(gid+16)  *64 + c0 + 4]);
        a1[3] = to_tf32(zs[(gid+24)  *64 + c0 + 4]);
        #pragma unroll
        for (int nb=0; nb<4; nb++){
            float2 b = BF[(kf*4 + nb)*32 + l];
            mma_tf32(acc[0][nb], a0, b.x, b.y);
            mma_tf32(acc[1][nb], a1, b.x, b.y);
        }
    }

    #pragma unroll
    for (int mt=0; mt<2; mt++){
        #pragma unroll
        for (int nb=0; nb<4; nb++){
            int col = w*32 + nb*8 + tig*2;
            float b0 = bsm[col], b1 = bsm[col+1];
            size_t row0 = (size_t)(r0 + mt*16 + gid);
            size_t row1 = row0 + 8;
            float2 o0 = make_float2(acc[mt][nb][0]+b0, acc[mt][nb][1]+b1);
            float2 o1 = make_float2(acc[mt][nb][2]+b0, acc[mt][nb][3]+b1);
            *(float2*)&g_gih[(row0*10 + p)*256 + col] = o0;
            *(float2*)&g_gih[(row1*10 + p)*256 + col] = o1;
        }
    }
}

// ------------------------------------------------------------------
// Kernel 3: LSTM recurrence. GPB=8 games/block, scalar math,
// reg-capped for 2 blocks/SM. grid = PP*(BG/8) = 320.
// ------------------------------------------------------------------
__global__ __launch_bounds__(256, 2) void lstm_kernel(
    const float* __restrict__ Whh, float* __restrict__ out)
{
    __shared__ float hs[GPB][64];
    __shared__ float gsm[GPB][256];

    const int p     = blockIdx.x >> 5;        // 0..9
    const int chunk = blockIdx.x & 31;        // 0..31
    const int b0    = chunk*GPB;
    const int gt    = threadIdx.x;
    const int gm    = gt >> 6;
    const int j     = gt & 63;

    float wreg[64];
    {
        const float* Wp = Whh + (size_t)p*16384 + gt*64;
        #pragma unroll
        for (int k=0;k<64;k+=4){
            float4 w4 = *(const float4*)&Wp[k];
            wreg[k+0]=w4.x; wreg[k+1]=w4.y; wreg[k+2]=w4.z; wreg[k+3]=w4.w;
        }
    }
    ((float*)hs)[gt] = 0.f;
    ((float*)hs)[gt+256] = 0.f;
    float creg0 = 0.f, creg1 = 0.f;
    __syncthreads();

    float pf[GPB];
    #pragma unroll
    for (int g=0; g<GPB; g++)
        pf[g] = g_gih[((size_t)(b0+g)*64*10 + p)*256 + gt];

    for (int t=0; t<TT; t++){
        float acc[GPB];
        #pragma unroll
        for (int g=0; g<GPB; g++) acc[g] = pf[g];

        #pragma unroll
        for (int k0=0;k0<64;k0+=4){
            float w0 = wreg[k0], w1 = wreg[k0+1], w2 = wreg[k0+2], w3 = wreg[k0+3];
            #pragma unroll
            for (int g=0; g<GPB; g++){
                float4 h = *(const float4*)&hs[g][k0];
                acc[g] += w0*h.x + w1*h.y + w2*h.z + w3*h.w;
            }
        }
        if (t < TT-1){
            #pragma unroll
            for (int g=0; g<GPB; g++)
                pf[g] = g_gih[(((size_t)(b0+g)*64 + t+1)*10 + p)*256 + gt];
        }
        #pragma unroll
        for (int g=0; g<GPB; g++) gsm[g][gt] = acc[g];
        __syncthreads();
        {
            float ig = sigmoid_fast(gsm[gm][j]);
            float fg = sigmoid_fast(gsm[gm][64+j]);
            float gg = tanh_fast   (gsm[gm][128+j]);
            float og = sigmoid_fast(gsm[gm][192+j]);
            creg0 = fg*creg0 + ig*gg;
            float h = og*tanh_fast(creg0);
            hs[gm][j] = h;
            out[(((size_t)(b0+gm)*64 + t)*10 + p)*64 + j] = h;

            int g2 = gm + 4;
            ig = sigmoid_fast(gsm[g2][j]);
            fg = sigmoid_fast(gsm[g2][64+j]);
            gg = tanh_fast   (gsm[g2][128+j]);
            og = sigmoid_fast(gsm[g2][192+j]);
            creg1 = fg*creg1 + ig*gg;
            h = og*tanh_fast(creg1);
            hs[g2][j] = h;
            out[(((size_t)(b0+g2)*64 + t)*10 + p)*64 + j] = h;
        }
        __syncthreads();
    }
}

// ------------------------------------------------------------------
extern "C" void kernel_launch(void* const* d_in, const int* in_sizes, int n_in,
                              void* d_out, int out_size)
{
    const float* x    = (const float*)d_in[0];
    const float* Apos = (const float*)d_in[1];
    const float* Aneg = (const float*)d_in[2];
    const float* Wpb  = (const float*)d_in[3];
    const float* bpb  = (const float*)d_in[4];
    const float* Wnb  = (const float*)d_in[5];
    const float* bnb  = (const float*)d_in[6];
    const float* Wpd  = (const float*)d_in[7];
    const float* bpd  = (const float*)d_in[8];
    const float* Wnd  = (const float*)d_in[9];
    const float* bnd  = (const float*)d_in[10];
    const float* Wih  = (const float*)d_in[11];
    const float* Whh  = (const float*)d_in[12];
    const float* bih  = (const float*)d_in[13];
    const float* bhh  = (const float*)d_in[14];
    float* out = (float*)d_out;

    const int nW = 4096 + 7168 + PP*8*8*4*32;
    transform_weights<<<(nW + 255)/256, 256>>>(Wpb, Wnb, Wpd, Wnd, Wih);

    sgcn_kernel<<<BT, 256>>>(x, Apos, Aneg, bpb, bnb, bpd, bnd);

    dim3 gg(BT/32, PP);
    gih_kernel<<<gg, 256>>>(bih, bhh);

    lstm_kernel<<<PP*(BG/GPB), 256>>>(Whh, out);   // 320 blocks
}

// round 17
// speedup vs baseline: 1.7691x; 1.7691x over previous
#include <cuda_runtime.h>
#include <math.h>

#define BG 256
#define TT 64
#define PP 10
#define DD 128
#define HH 64
#define BT (BG*TT)   // 16384
#define ZP 68        // padded z-tile row stride (bank-conflict-free)

// ---- device scratch (allocation-free) ----
__device__ float g_z[BT*PP*64];            // SGCN output z  [bt][p][64]
__device__ float g_gih[(size_t)BT*PP*256]; // gates_ih+bias  [bt][p][256]
__device__ float4 g_WbF[4096];             // base W tf32 frags [s][q][kf][fp][lane]
__device__ float4 g_WdF[7168];             // deep W tf32 frags [s][layer][q][kf][fp][lane]
__device__ float2 g_WihF[PP*8*8*4*32];     // gih B frags [p][w][kf][nb][lane]

// ---- tf32 helpers ----
__device__ __forceinline__ float to_tf32(float x){
    float y; asm("cvt.rna.tf32.f32 %0, %1;" : "=f"(y) : "f"(x)); return y;
}
// D = A(16x8,row) * B(8x8,col) + D, tf32 inputs, f32 accum
__device__ __forceinline__ void mma_tf32(float* c, const float* a, float b0, float b1){
    const unsigned* A = (const unsigned*)a;
    unsigned B0 = __float_as_uint(b0), B1 = __float_as_uint(b1);
    asm volatile(
        "mma.sync.aligned.m16n8k8.row.col.f32.tf32.tf32.f32 "
        "{%0,%1,%2,%3}, {%4,%5,%6,%7}, {%8,%9}, {%0,%1,%2,%3};\n"
        : "+f"(c[0]), "+f"(c[1]), "+f"(c[2]), "+f"(c[3])
        : "r"(A[0]), "r"(A[1]), "r"(A[2]), "r"(A[3]), "r"(B0), "r"(B1));
}

// fast activations
__device__ __forceinline__ float tanh_mufu(float x){
    float y; asm("tanh.approx.f32 %0, %1;" : "=f"(y) : "f"(x)); return y;
}
__device__ __forceinline__ float sigmoid_fast(float v){
    return __fdividef(1.0f, 1.0f + __expf(-v));
}
__device__ __forceinline__ float tanh_fast(float v){
    return __fdividef(2.0f, 1.0f + __expf(-2.0f*v)) - 1.0f;
}

// ------------------------------------------------------------------
// Kernel 0: weight packing -> tf32 mma B-fragments (base, deep, W_ih)
// ------------------------------------------------------------------
__global__ void transform_weights(
    const float* __restrict__ Wpb, const float* __restrict__ Wnb,
    const float* __restrict__ Wpd, const float* __restrict__ Wnd,
    const float* __restrict__ Wih)
{
    int idx = blockIdx.x*blockDim.x + threadIdx.x;
    if (idx < 4096){
        // base B frags: [s][q][kf][fp][lane]
        int lane = idx & 31; int t = idx >> 5;
        int fp = t & 1; t >>= 1;
        int kf = t & 7; t >>= 3;
        int q  = t & 3; int s = t >> 2;
        const float* W = s ? Wnb : Wpb;           // [256][32]
        int kb = q*64 + kf*8 + (lane & 3);
        int n0 = lane >> 2;
        int f0 = fp*2, f1 = fp*2 + 1;
        g_WbF[idx] = make_float4(
            to_tf32(W[(kb  )*32 + f0*8 + n0]), to_tf32(W[(kb+4)*32 + f0*8 + n0]),
            to_tf32(W[(kb  )*32 + f1*8 + n0]), to_tf32(W[(kb+4)*32 + f1*8 + n0]));
    } else if (idx < 4096 + 7168){
        // deep B frags: [s][layer][q][kf][fp][lane]
        int i2 = idx - 4096;
        int lane = i2 & 31; int t = i2 >> 5;
        int fp = t & 1; t >>= 1;
        int kf = t % 7; t /= 7;
        int q  = t & 3; t >>= 2;
        int layer = t & 1; int s = t >> 1;
        const float* W = (s ? Wnd : Wpd) + layer*224*32;   // [224][32]
        int kb = q*56 + kf*8 + (lane & 3);
        int n0 = lane >> 2;
        int f0 = fp*2, f1 = fp*2 + 1;
        g_WdF[i2] = make_float4(
            to_tf32(W[(kb  )*32 + f0*8 + n0]), to_tf32(W[(kb+4)*32 + f0*8 + n0]),
            to_tf32(W[(kb  )*32 + f1*8 + n0]), to_tf32(W[(kb+4)*32 + f1*8 + n0]));
    } else if (idx < 4096 + 7168 + PP*8*8*4*32){
        // gih B frags: [p][w][kf][nb][lane];  B[k][n] = Wih[p][n][k]
        int i3 = idx - (4096 + 7168);
        int lane = i3 & 31; int t = i3 >> 5;
        int nb = t & 3; t >>= 2;
        int kf = t & 7; t >>= 3;
        int w  = t & 7; int p = t >> 3;
        int g0 = w*32 + nb*8 + (lane >> 2);
        int k  = kf*8 + (lane & 3);
        const float* W = Wih + (size_t)p*16384 + g0*64;
        g_WihF[i3] = make_float2(to_tf32(W[k]), to_tf32(W[k+4]));
    }
}

// ------------------------------------------------------------------
// Kernel 1: SGCN (exact Round-14 version — tf32 mma, passed).
// ------------------------------------------------------------------
__global__ __launch_bounds__(256) void sgcn_kernel(
    const float* __restrict__ x,
    const float* __restrict__ Apos, const float* __restrict__ Aneg,
    const float* __restrict__ bpb,  const float* __restrict__ bnb,
    const float* __restrict__ bpd,  const float* __restrict__ bnd)
{
    __shared__ __align__(16) float xs[PP*DD];
    __shared__ float Asm[2][PP*PP];
    __shared__ float rs[2][PP];
    __shared__ __align__(16) float aggx[2*PP*DD];
    __shared__ __align__(16) float cat[6*PP*32];
    __shared__ float part[4*2*PP*32];

    const int bt  = blockIdx.x;
    const int tid = threadIdx.x;
    const int w   = tid >> 5;
    const int l   = tid & 31;
    const int s   = w & 1;
    const int q   = w >> 1;
    const int gid = l >> 2;
    const int tig = l & 3;

    {
        const float4* x4 = (const float4*)(x + (size_t)bt*PP*DD);
        float4* xs4 = (float4*)xs;
        for (int i = tid; i < PP*DD/4; i += 256) xs4[i] = x4[i];
    }
    if (tid < 200){
        int ss = tid/100, idx = tid - ss*100;
        Asm[ss][idx] = (ss ? Aneg : Apos)[(size_t)bt*100 + idx];
    }
    __syncthreads();
    if (tid < 20){
        int ss = tid/10, r = tid - ss*10;
        float sum = 0.f;
        #pragma unroll
        for (int j=0;j<10;j++) sum += Asm[ss][r*10+j];
        rs[ss][r] = __fdividef(1.0f, sum + 1e-8f);
    }
    __syncthreads();
    if (tid < 200){
        int ss = tid/100, idx = tid - ss*100;
        Asm[ss][idx] *= rs[ss][idx/10];
    }
    __syncthreads();

    {
        float4* ag4 = (float4*)aggx;
        const float4* xs4 = (const float4*)xs;
        for (int o = tid; o < 2*PP*32; o += 256){
            int ss = o / 320; int rem = o - ss*320;
            int r = rem >> 5; int d4 = rem & 31;
            float4 sum = make_float4(0.f,0.f,0.f,0.f);
            #pragma unroll
            for (int j=0;j<10;j++){
                float a = Asm[ss][r*10+j];
                float4 xv = xs4[j*32 + d4];
                sum.x += a*xv.x; sum.y += a*xv.y; sum.z += a*xv.z; sum.w += a*xv.w;
            }
            ag4[o] = sum;
        }
    }
    __syncthreads();

    // base matmul (tensor cores)
    {
        const float* src = (q < 2) ? (aggx + s*1280 + q*64) : (xs + (q-2)*64);
        float a[8][4];
        #pragma unroll
        for (int kf=0; kf<8; kf++){
            int c0 = kf*8 + tig;
            a[kf][0] = to_tf32(src[gid*128 + c0]);
            a[kf][1] = (gid<2) ? to_tf32(src[(gid+8)*128 + c0]) : 0.f;
            a[kf][2] = to_tf32(src[gid*128 + c0 + 4]);
            a[kf][3] = (gid<2) ? to_tf32(src[(gid+8)*128 + c0 + 4]) : 0.f;
        }
        float acc[4][4];
        #pragma unroll
        for (int f=0; f<4; f++){
            #pragma unroll
            for (int e=0; e<4; e++) acc[f][e] = 0.f;
        }
        const float4* BF = g_WbF + (size_t)((s*4+q)*8)*2*32;
        #pragma unroll
        for (int kf=0; kf<8; kf++){
            float4 b01 = BF[(kf*2+0)*32 + l];
            float4 b23 = BF[(kf*2+1)*32 + l];
            mma_tf32(acc[0], a[kf], b01.x, b01.y);
            mma_tf32(acc[1], a[kf], b01.z, b01.w);
            mma_tf32(acc[2], a[kf], b23.x, b23.y);
            mma_tf32(acc[3], a[kf], b23.z, b23.w);
        }
        float* pp = part + ((q*2+s)*10)*32;
        #pragma unroll
        for (int f=0; f<4; f++){
            int n0 = f*8 + tig*2;
            pp[gid*32 + n0]     = acc[f][0];
            pp[gid*32 + n0 + 1] = acc[f][1];
            if (gid < 2){
                pp[(gid+8)*32 + n0]     = acc[f][2];
                pp[(gid+8)*32 + n0 + 1] = acc[f][3];
            }
        }
    }
    __syncthreads();
    for (int o=tid; o<640; o+=256){
        int ss = o/320, rem = o - ss*320, r = rem>>5, col = rem&31;
        float v = (ss ? bnb : bpb)[col];
        #pragma unroll
        for (int qq=0;qq<4;qq++) v += part[((qq*2+ss)*10+r)*32+col];
        cat[(4+ss)*320 + r*32 + col] = tanh_mufu(v);
    }
    __syncthreads();

    for (int layer=0; layer<2; layer++){
        for (int o=tid; o<320; o+=256){
            int m = o/80, rem = o - m*80, r = rem>>3, c4 = (rem&7)*4;
            int as = m>>1, hsn = m&1;
            float4 sum = make_float4(0.f,0.f,0.f,0.f);
            #pragma unroll
            for (int j=0;j<10;j++){
                float a = Asm[as][r*10+j];
                float4 h = *(const float4*)&cat[(4+hsn)*320 + j*32 + c4];
                sum.x += a*h.x; sum.y += a*h.y; sum.z += a*h.z; sum.w += a*h.w;
            }
            *(float4*)&cat[m*320 + r*32 + c4] = sum;
        }
        __syncthreads();
        {
            float a[7][4];
            #pragma unroll
            for (int kf=0; kf<7; kf++){
                int k0 = q*56 + kf*8;
                int blk = k0 >> 5, ko = k0 & 31;
                const float* srcp = cat + ((blk<6) ? blk : (4+s))*320;
                int c0 = ko + tig;
                a[kf][0] = to_tf32(srcp[gid*32 + c0]);
                a[kf][1] = (gid<2) ? to_tf32(srcp[(gid+8)*32 + c0]) : 0.f;
                a[kf][2] = to_tf32(srcp[gid*32 + c0 + 4]);
                a[kf][3] = (gid<2) ? to_tf32(srcp[(gid+8)*32 + c0 + 4]) : 0.f;
            }
            float acc[4][4];
            #pragma unroll
            for (int f=0; f<4; f++){
                #pragma unroll
                for (int e=0; e<4; e++) acc[f][e] = 0.f;
            }
            const float4* BF = g_WdF + (size_t)(((s*2+layer)*4 + q)*7)*2*32;
            #pragma unroll
            for (int kf=0; kf<7; kf++){
                float4 b01 = BF[(kf*2+0)*32 + l];
                float4 b23 = BF[(kf*2+1)*32 + l];
                mma_tf32(acc[0], a[kf], b01.x, b01.y);
                mma_tf32(acc[1], a[kf], b01.z, b01.w);
                mma_tf32(acc[2], a[kf], b23.x, b23.y);
                mma_tf32(acc[3], a[kf], b23.z, b23.w);
            }
            float* pp = part + ((q*2+s)*10)*32;
            #pragma unroll
            for (int f=0; f<4; f++){
                int n0 = f*8 + tig*2;
                pp[gid*32 + n0]     = acc[f][0];
                pp[gid*32 + n0 + 1] = acc[f][1];
                if (gid < 2){
                    pp[(gid+8)*32 + n0]     = acc[f][2];
                    pp[(gid+8)*32 + n0 + 1] = acc[f][3];
                }
            }
        }
        __syncthreads();
        for (int o=tid; o<640; o+=256){
            int ss = o/320, rem = o - ss*320, r = rem>>5, col = rem&31;
            float v = (ss ? bnd : bpd)[layer*32+col];
            #pragma unroll
            for (int qq=0;qq<4;qq++) v += part[((qq*2+ss)*10+r)*32+col];
            cat[(4+ss)*320 + r*32 + col] = tanh_mufu(v);
        }
        __syncthreads();
    }

    float* zo = g_z + (size_t)bt*PP*64;
    for (int o=tid; o<640; o+=256){
        int r = o>>6, c = o&63, ss = c>>5, cc = c&31;
        zo[o] = cat[(4+ss)*320 + r*32 + cc];
    }
}

// ------------------------------------------------------------------
// Kernel 2: gates_ih on tensor cores — zs padded to stride 68
// (conflict-free: bank = gid*4+tig = lane).
// Block = (p, 32 rows), 8 warps; warp w covers gates [w*32, w*32+32).
// grid: (BT/32, PP) = (512, 10).
// ------------------------------------------------------------------
__global__ __launch_bounds__(256) void gih_kernel(
    const float* __restrict__ bih, const float* __restrict__ bhh)
{
    __shared__ __align__(16) float zs[32*ZP];   // padded rows
    __shared__ float bsm[256];

    const int p   = blockIdx.y;
    const int r0  = blockIdx.x * 32;
    const int tid = threadIdx.x;
    const int w   = tid >> 5;
    const int l   = tid & 31;
    const int gid = l >> 2;
    const int tig = l & 3;

    {   // z tile: 512 float4 into padded rows
        for (int i = tid; i < 512; i += 256){
            int rr = i >> 4, d4 = i & 15;
            float4 v = *(const float4*)&g_z[((size_t)(r0+rr)*10 + p)*64 + d4*4];
            *(float4*)&zs[rr*ZP + d4*4] = v;
        }
    }
    bsm[tid] = bih[p*256+tid] + bhh[p*256+tid];
    __syncthreads();

    float acc[2][4][4];
    #pragma unroll
    for (int mt=0; mt<2; mt++)
        #pragma unroll
        for (int nb=0; nb<4; nb++)
            #pragma unroll
            for (int e=0; e<4; e++) acc[mt][nb][e] = 0.f;

    const float2* BF = g_WihF + (size_t)(p*8 + w)*8*4*32;

    #pragma unroll
    for (int kf=0; kf<8; kf++){
        int c0 = kf*8 + tig;
        float a0[4], a1[4];
        a0[0] = to_tf32(zs[ gid      *ZP + c0]);
        a0[1] = to_tf32(zs[(gid+8)   *ZP + c0]);
        a0[2] = to_tf32(zs[ gid      *ZP + c0 + 4]);
        a0[3] = to_tf32(zs[(gid+8)   *ZP + c0 + 4]);
        a1[0] = to_tf32(zs[(gid+16)  *ZP + c0]);
        a1[1] = to_tf32(zs[(gid+24)  *ZP + c0]);
        a1[2] = to_tf32(zs[(gid+16)  *ZP + c0 + 4]);
        a1[3] = to_tf32(zs[(gid+24)  *ZP + c0 + 4]);
        #pragma unroll
        for (int nb=0; nb<4; nb++){
            float2 b = BF[(kf*4 + nb)*32 + l];
            mma_tf32(acc[0][nb], a0, b.x, b.y);
            mma_tf32(acc[1][nb], a1, b.x, b.y);
        }
    }

    #pragma unroll
    for (int mt=0; mt<2; mt++){
        #pragma unroll
        for (int nb=0; nb<4; nb++){
            int col = w*32 + nb*8 + tig*2;
            float b0 = bsm[col], b1 = bsm[col+1];
            size_t row0 = (size_t)(r0 + mt*16 + gid);
            size_t row1 = row0 + 8;
            float2 o0 = make_float2(acc[mt][nb][0]+b0, acc[mt][nb][1]+b1);
            float2 o1 = make_float2(acc[mt][nb][2]+b0, acc[mt][nb][3]+b1);
            *(float2*)&g_gih[(row0*10 + p)*256 + col] = o0;
            *(float2*)&g_gih[(row1*10 + p)*256 + col] = o1;
        }
    }
}

// ------------------------------------------------------------------
// Kernel 3: LSTM recurrence (exact Round-3 version, known 233us).
// One block per (p, 4-game chunk). grid = 640.
// ------------------------------------------------------------------
__global__ __launch_bounds__(256) void lstm_kernel(
    const float* __restrict__ Whh, float* __restrict__ out)
{
    __shared__ float hs[4][64];
    __shared__ float gsm[4][256];

    const int p     = blockIdx.x >> 6;
    const int chunk = blockIdx.x & 63;
    const int b0    = chunk*4;
    const int gt    = threadIdx.x;
    const int gm    = gt >> 6;
    const int j     = gt & 63;

    float wreg[64];
    {
        const float* Wp = Whh + (size_t)p*16384 + gt*64;
        #pragma unroll
        for (int k=0;k<64;k+=4){
            float4 w4 = *(const float4*)&Wp[k];
            wreg[k+0]=w4.x; wreg[k+1]=w4.y; wreg[k+2]=w4.z; wreg[k+3]=w4.w;
        }
    }
    ((float*)hs)[gt] = 0.f;
    float creg = 0.f;
    __syncthreads();

    float pf[4];
    #pragma unroll
    for (int g4=0; g4<4; g4++)
        pf[g4] = g_gih[((size_t)(b0+g4)*64*10 + p)*256 + gt];

    for (int t=0; t<TT; t++){
        float acc0 = pf[0], acc1 = pf[1], acc2 = pf[2], acc3 = pf[3];
        #pragma unroll
        for (int k0=0;k0<64;k0+=4){
            float4 h0 = *(const float4*)&hs[0][k0];
            float4 h1 = *(const float4*)&hs[1][k0];
            float4 h2 = *(const float4*)&hs[2][k0];
            float4 h3 = *(const float4*)&hs[3][k0];
            float w0 = wreg[k0], w1 = wreg[k0+1], w2 = wreg[k0+2], w3 = wreg[k0+3];
            acc0 += w0*h0.x + w1*h0.y + w2*h0.z + w3*h0.w;
            acc1 += w0*h1.x + w1*h1.y + w2*h1.z + w3*h1.w;
            acc2 += w0*h2.x + w1*h2.y + w2*h2.z + w3*h2.w;
            acc3 += w0*h3.x + w1*h3.y + w2*h3.z + w3*h3.w;
        }
        if (t < TT-1){
            #pragma unroll
            for (int g4=0; g4<4; g4++)
                pf[g4] = g_gih[(((size_t)(b0+g4)*64 + t+1)*10 + p)*256 + gt];
        }
        gsm[0][gt] = acc0; gsm[1][gt] = acc1; gsm[2][gt] = acc2; gsm[3][gt] = acc3;
        __syncthreads();
        {
            float ig = sigmoid_fast(gsm[gm][j]);
            float fg = sigmoid_fast(gsm[gm][64+j]);
            float gg = tanh_fast   (gsm[gm][128+j]);
            float og = sigmoid_fast(gsm[gm][192+j]);
            creg = fg*creg + ig*gg;
            float h = og*tanh_fast(creg);
            hs[gm][j] = h;
            size_t bt = (size_t)(b0+gm)*64 + t;
            out[(bt*10 + p)*64 + j] = h;
        }
        __syncthreads();
    }
}

// ------------------------------------------------------------------
extern "C" void kernel_launch(void* const* d_in, const int* in_sizes, int n_in,
                              void* d_out, int out_size)
{
    const float* x    = (const float*)d_in[0];
    const float* Apos = (const float*)d_in[1];
    const float* Aneg = (const float*)d_in[2];
    const float* Wpb  = (const float*)d_in[3];
    const float* bpb  = (const float*)d_in[4];
    const float* Wnb  = (const float*)d_in[5];
    const float* bnb  = (const float*)d_in[6];
    const float* Wpd  = (const float*)d_in[7];
    const float* bpd  = (const float*)d_in[8];
    const float* Wnd  = (const float*)d_in[9];
    const float* bnd  = (const float*)d_in[10];
    const float* Wih  = (const float*)d_in[11];
    const float* Whh  = (const float*)d_in[12];
    const float* bih  = (const float*)d_in[13];
    const float* bhh  = (const float*)d_in[14];
    float* out = (float*)d_out;

    const int nW = 4096 + 7168 + PP*8*8*4*32;
    transform_weights<<<(nW + 255)/256, 256>>>(Wpb, Wnb, Wpd, Wnd, Wih);

    sgcn_kernel<<<BT, 256>>>(x, Apos, Aneg, bpb, bnb, bpd, bnd);

    dim3 gg(BT/32, PP);
    gih_kernel<<<gg, 256>>>(bih, bhh);

    lstm_kernel<<<PP*(BG/4), 256>>>(Whh, out);   // 640 blocks
}